// round 1
// baseline (speedup 1.0000x reference)
#include <cuda_runtime.h>
#include <math.h>

// Problem constants (fixed shapes from reference)
#define NE 8          // experts
#define HD 1024       // hidden
#define FD 4096       // ffn
#define NT 8192       // token copies (tokens * topk)
#define NOUT (NT / 2) // output rows after topk reduce

// GEMM tile config
#define BM 128
#define BN 128
#define BK 8

// Scratch (allocation-free rule: __device__ globals)
__device__ float g_hbuf[(size_t)NT * FD];   // gelu(fc1) activations, sorted order (134 MB)
__device__ int   g_perm[NT];                // g_perm[slot] = original token-copy index
__device__ int   g_cnt[NE];
__device__ int   g_cur[NE];
__device__ int   g_off[NE + 1];

__device__ __forceinline__ float gelu_exact(float v) {
    return 0.5f * v * (1.0f + erff(v * 0.7071067811865476f));
}

// ---------------- routing: counting sort by expert ----------------

__global__ void k_zero() {
    int t = threadIdx.x;
    if (t < NE) { g_cnt[t] = 0; g_cur[t] = 0; }
}

__global__ void k_count(const int* __restrict__ ex) {
    int i = blockIdx.x * blockDim.x + threadIdx.x;
    if (i < NT) atomicAdd(&g_cnt[ex[i]], 1);
}

__global__ void k_scan() {
    // one thread, E=8
    int s = 0;
    for (int e = 0; e < NE; e++) { g_off[e] = s; s += g_cnt[e]; }
    g_off[NE] = s;
}

__global__ void k_scatter(const int* __restrict__ ex) {
    int i = blockIdx.x * blockDim.x + threadIdx.x;
    if (i < NT) {
        int e = ex[i];
        int r = atomicAdd(&g_cur[e], 1);
        g_perm[g_off[e] + r] = i;
    }
}

// ---------------- fc1: H = gelu(X @ W1^T), grouped by expert ----------------
// A: gathered rows of x [mlen, HD] (K-contiguous)
// B: w1[e] rows [FD, HD]           (K-contiguous)  -> NT gemm

__global__ __launch_bounds__(256, 2)
void k_fc1(const float* __restrict__ x, const float* __restrict__ w1) {
    __shared__ float As[BK][BM];
    __shared__ float Bs[BK][BN];

    const int e    = blockIdx.z;
    const int seg0 = g_off[e];
    const int mlen = g_off[e + 1] - seg0;
    const int m0   = blockIdx.y * BM;
    if (m0 >= mlen) return;
    const int n0   = blockIdx.x * BN;

    const int tid  = threadIdx.x;
    const int lrow = tid >> 1;          // 0..127
    const int lk   = (tid & 1) * 4;     // 0 or 4

    const float* aptr = nullptr;
    if (m0 + lrow < mlen)
        aptr = x + (size_t)g_perm[seg0 + m0 + lrow] * HD + lk;
    const float* bptr = w1 + (size_t)e * FD * HD + (size_t)(n0 + lrow) * HD + lk;

    float4 av = aptr ? *(const float4*)aptr : make_float4(0.f, 0.f, 0.f, 0.f);
    float4 bv = *(const float4*)bptr;

    float acc[8][8];
#pragma unroll
    for (int i = 0; i < 8; i++)
#pragma unroll
        for (int j = 0; j < 8; j++) acc[i][j] = 0.f;

    const int tx = (tid & 15) * 8;   // col base in tile
    const int ty = (tid >> 4) * 8;   // row base in tile

    for (int k0 = BK; k0 <= HD; k0 += BK) {
        __syncthreads();
        As[lk + 0][lrow] = av.x; As[lk + 1][lrow] = av.y;
        As[lk + 2][lrow] = av.z; As[lk + 3][lrow] = av.w;
        Bs[lk + 0][lrow] = bv.x; Bs[lk + 1][lrow] = bv.y;
        Bs[lk + 2][lrow] = bv.z; Bs[lk + 3][lrow] = bv.w;
        __syncthreads();
        if (k0 < HD) {
            av = aptr ? *(const float4*)(aptr + k0) : make_float4(0.f, 0.f, 0.f, 0.f);
            bv = *(const float4*)(bptr + k0);
        }
#pragma unroll
        for (int k = 0; k < BK; k++) {
            float a[8], b[8];
            *(float4*)&a[0] = *(const float4*)&As[k][ty];
            *(float4*)&a[4] = *(const float4*)&As[k][ty + 4];
            *(float4*)&b[0] = *(const float4*)&Bs[k][tx];
            *(float4*)&b[4] = *(const float4*)&Bs[k][tx + 4];
#pragma unroll
            for (int i = 0; i < 8; i++)
#pragma unroll
                for (int j = 0; j < 8; j++)
                    acc[i][j] = fmaf(a[i], b[j], acc[i][j]);
        }
    }

#pragma unroll
    for (int i = 0; i < 8; i++) {
        int lr = m0 + ty + i;
        if (lr < mlen) {
            float* hrow = g_hbuf + (size_t)(seg0 + lr) * FD + n0 + tx;
            float4 v0, v1;
            v0.x = gelu_exact(acc[i][0]); v0.y = gelu_exact(acc[i][1]);
            v0.z = gelu_exact(acc[i][2]); v0.w = gelu_exact(acc[i][3]);
            v1.x = gelu_exact(acc[i][4]); v1.y = gelu_exact(acc[i][5]);
            v1.z = gelu_exact(acc[i][6]); v1.w = gelu_exact(acc[i][7]);
            *(float4*)hrow       = v0;
            *(float4*)(hrow + 4) = v1;
        }
    }
}

// ---------------- fc2: Y = H @ W2^T, scale by gate, scatter-add to out ----------------
// A: g_hbuf rows [mlen, FD] (K-contiguous)
// B: w2[e] rows [HD, FD]    (K-contiguous)

__global__ __launch_bounds__(256, 2)
void k_fc2(const float* __restrict__ gate, const int* __restrict__ new_index,
           const float* __restrict__ w2, float* __restrict__ out) {
    __shared__ float As[BK][BM];
    __shared__ float Bs[BK][BN];

    const int e    = blockIdx.z;
    const int seg0 = g_off[e];
    const int mlen = g_off[e + 1] - seg0;
    const int m0   = blockIdx.y * BM;
    if (m0 >= mlen) return;
    const int n0   = blockIdx.x * BN;

    const int tid  = threadIdx.x;
    const int lrow = tid >> 1;
    const int lk   = (tid & 1) * 4;

    const float* aptr = nullptr;
    if (m0 + lrow < mlen)
        aptr = g_hbuf + (size_t)(seg0 + m0 + lrow) * FD + lk;
    const float* bptr = w2 + (size_t)e * HD * FD + (size_t)(n0 + lrow) * FD + lk;

    float4 av = aptr ? *(const float4*)aptr : make_float4(0.f, 0.f, 0.f, 0.f);
    float4 bv = *(const float4*)bptr;

    float acc[8][8];
#pragma unroll
    for (int i = 0; i < 8; i++)
#pragma unroll
        for (int j = 0; j < 8; j++) acc[i][j] = 0.f;

    const int tx = (tid & 15) * 8;
    const int ty = (tid >> 4) * 8;

    for (int k0 = BK; k0 <= FD; k0 += BK) {
        __syncthreads();
        As[lk + 0][lrow] = av.x; As[lk + 1][lrow] = av.y;
        As[lk + 2][lrow] = av.z; As[lk + 3][lrow] = av.w;
        Bs[lk + 0][lrow] = bv.x; Bs[lk + 1][lrow] = bv.y;
        Bs[lk + 2][lrow] = bv.z; Bs[lk + 3][lrow] = bv.w;
        __syncthreads();
        if (k0 < FD) {
            av = aptr ? *(const float4*)(aptr + k0) : make_float4(0.f, 0.f, 0.f, 0.f);
            bv = *(const float4*)(bptr + k0);
        }
#pragma unroll
        for (int k = 0; k < BK; k++) {
            float a[8], b[8];
            *(float4*)&a[0] = *(const float4*)&As[k][ty];
            *(float4*)&a[4] = *(const float4*)&As[k][ty + 4];
            *(float4*)&b[0] = *(const float4*)&Bs[k][tx];
            *(float4*)&b[4] = *(const float4*)&Bs[k][tx + 4];
#pragma unroll
            for (int i = 0; i < 8; i++)
#pragma unroll
                for (int j = 0; j < 8; j++)
                    acc[i][j] = fmaf(a[i], b[j], acc[i][j]);
        }
    }

#pragma unroll
    for (int i = 0; i < 8; i++) {
        int lr = m0 + ty + i;
        if (lr < mlen) {
            int   orig = g_perm[seg0 + lr];
            float g    = gate[orig];
            int   dest = new_index[orig];
            float* orow = out + (size_t)(dest >> 1) * HD + n0 + tx;
#pragma unroll
            for (int j = 0; j < 8; j++)
                atomicAdd(&orow[j], acc[i][j] * g);
        }
    }
}

// ---------------- launch ----------------

extern "C" void kernel_launch(void* const* d_in, const int* in_sizes, int n_in,
                              void* d_out, int out_size) {
    const float* x         = (const float*)d_in[0];  // [NT, HD]
    const float* gate      = (const float*)d_in[1];  // [NT]
    const int*   experts   = (const int*)  d_in[2];  // [NT]
    const int*   new_index = (const int*)  d_in[3];  // [NT]
    const float* w1        = (const float*)d_in[4];  // [NE, FD, HD]
    const float* w2        = (const float*)d_in[5];  // [NE, HD, FD]
    float*       out       = (float*)d_out;          // [NOUT, HD]

    cudaMemsetAsync(d_out, 0, (size_t)out_size * sizeof(float), 0);

    k_zero<<<1, 32>>>();
    k_count<<<NT / 256, 256>>>(experts);
    k_scan<<<1, 1>>>();
    k_scatter<<<NT / 256, 256>>>(experts);

    // fc1: per expert, M tiles cover worst-case skew (all tokens in one expert)
    k_fc1<<<dim3(FD / BN, NT / BM, NE), 256>>>(x, w1);
    // fc2 + gate scale + scatter/topk-reduce
    k_fc2<<<dim3(HD / BN, NT / BM, NE), 256>>>(gate, new_index, w2, out);
}

// round 3
// speedup vs baseline: 2.8828x; 2.8828x over previous
#include <cuda_runtime.h>
#include <math.h>
#include <stdint.h>

// ---------------- problem constants ----------------
#define NE 8
#define HD 1024
#define FD 4096
#define NT 8192

// ---------------- GEMM tile config ----------------
#define BM 128
#define BN 256
#define BK 32
#define STAGES 3
#define A_STAGE_BYTES (BM * BK * 4)             // 16384
#define B_STAGE_BYTES (BN * BK * 4)             // 32768
#define STAGE_BYTES   (A_STAGE_BYTES + B_STAGE_BYTES)  // 49152
#define SMEM_BYTES    (STAGES * STAGE_BYTES)           // 147456

// ---------------- device scratch (allocation-free rule) ----------------
__device__ __align__(16) float g_w1t[(size_t)NE * FD * HD];  // tf32-rounded w1
__device__ __align__(16) float g_w2t[(size_t)NE * HD * FD];  // tf32-rounded w2
__device__ __align__(16) float g_xt[(size_t)NT * HD];        // tf32-rounded x
__device__ __align__(16) float g_hbuf[(size_t)NT * FD];      // gelu(fc1), rounded, sorted order
__device__ int g_perm[NT];
__device__ int g_cnt[NE], g_cur[NE], g_off[NE + 1];

// ---------------- helpers ----------------
__device__ __forceinline__ uint32_t smem_u32(const void* p) {
    uint32_t a;
    asm("{ .reg .u64 t; cvta.to.shared.u64 t, %1; cvt.u32.u64 %0, t; }" : "=r"(a) : "l"(p));
    return a;
}
__device__ __forceinline__ float f2tf32(float f) {
    uint32_t r;
    asm("cvt.rna.tf32.f32 %0, %1;" : "=r"(r) : "f"(f));
    return __uint_as_float(r);
}
__device__ __forceinline__ void cp16(uint32_t dst, const void* src) {
    asm volatile("cp.async.cg.shared.global [%0], [%1], 16;" :: "r"(dst), "l"(src));
}
__device__ __forceinline__ void cp_commit() {
    asm volatile("cp.async.commit_group;" ::: "memory");
}
template <int N>
__device__ __forceinline__ void cp_wait() {
    asm volatile("cp.async.wait_group %0;" :: "n"(N) : "memory");
}
__device__ __forceinline__ void ldsm_x4(uint32_t* r, uint32_t addr) {
    asm volatile("ldmatrix.sync.aligned.m8n8.x4.shared.b16 {%0,%1,%2,%3}, [%4];"
                 : "=r"(r[0]), "=r"(r[1]), "=r"(r[2]), "=r"(r[3]) : "r"(addr));
}
__device__ __forceinline__ void ldsm_x2(uint32_t* r, uint32_t addr) {
    asm volatile("ldmatrix.sync.aligned.m8n8.x2.shared.b16 {%0,%1}, [%2];"
                 : "=r"(r[0]), "=r"(r[1]) : "r"(addr));
}
__device__ __forceinline__ void mma_tf32(float* c, const uint32_t* a, const uint32_t* b) {
    asm volatile(
        "mma.sync.aligned.m16n8k8.row.col.f32.tf32.tf32.f32 "
        "{%0,%1,%2,%3}, {%4,%5,%6,%7}, {%8,%9}, {%0,%1,%2,%3};"
        : "+f"(c[0]), "+f"(c[1]), "+f"(c[2]), "+f"(c[3])
        : "r"(a[0]), "r"(a[1]), "r"(a[2]), "r"(a[3]), "r"(b[0]), "r"(b[1]));
}
__device__ __forceinline__ float gelu_exact(float v) {
    return 0.5f * v * (1.0f + erff(v * 0.7071067811865476f));
}

// ---------------- routing: counting sort by expert ----------------
__global__ void k_zero() {
    int t = threadIdx.x;
    if (t < NE) { g_cnt[t] = 0; g_cur[t] = 0; }
}
__global__ void k_count(const int* __restrict__ ex) {
    int i = blockIdx.x * blockDim.x + threadIdx.x;
    if (i < NT) atomicAdd(&g_cnt[ex[i]], 1);
}
__global__ void k_scan() {
    int s = 0;
    for (int e = 0; e < NE; e++) { g_off[e] = s; s += g_cnt[e]; }
    g_off[NE] = s;
}
__global__ void k_scatter(const int* __restrict__ ex) {
    int i = blockIdx.x * blockDim.x + threadIdx.x;
    if (i < NT) {
        int e = ex[i];
        int r = atomicAdd(&g_cur[e], 1);
        g_perm[g_off[e] + r] = i;
    }
}

// ---------------- tf32 pre-rounding (cvt.rna) ----------------
__global__ void k_cvt(const float4* __restrict__ src, float4* __restrict__ dst, int n4) {
    int i = blockIdx.x * blockDim.x + threadIdx.x;
    int stride = gridDim.x * blockDim.x;
    for (; i < n4; i += stride) {
        float4 v = src[i];
        v.x = f2tf32(v.x); v.y = f2tf32(v.y); v.z = f2tf32(v.z); v.w = f2tf32(v.w);
        dst[i] = v;
    }
}

// ---------------- tf32 mma.sync grouped GEMM ----------------
// FC1: A = gathered g_xt rows [mlen, HD], B = g_w1t[e] [FD, HD] -> gelu -> g_hbuf
// FC2: A = g_hbuf rows [mlen, FD],       B = g_w2t[e] [HD, FD] -> gate*scatter-add -> out

template <int KTOT, bool FC1>
__global__ __launch_bounds__(256, 1)
void k_gemm(const float* __restrict__ Agm,
            const float* __restrict__ Wgm,
            const float* __restrict__ gate,
            const int*   __restrict__ new_index,
            float*       __restrict__ outp)
{
    extern __shared__ __align__(128) char smem[];

    const int e    = blockIdx.z;
    const int seg0 = g_off[e];
    const int mlen = g_off[e + 1] - seg0;
    const int m0   = blockIdx.y * BM;
    if (m0 >= mlen) return;
    const int n0   = blockIdx.x * BN;

    const int tid = threadIdx.x;
    const int wid = tid >> 5;
    const int lid = tid & 31;
    const int wm  = wid & 1;       // m half: 0/1 (64 rows each)
    const int wn  = wid >> 1;      // n quarter: 0..3 (64 cols each)

    const uint32_t smem_b = smem_u32(smem);

    // ---- gmem load mapping: thread t -> A row t>>1 (c4 half t&1); B rows t>>1, t>>1+128 ----
    const int grow = tid >> 1;
    const int c4b  = (tid & 1) * 4;

    int arow_t = m0 + grow;
    if (arow_t >= mlen) arow_t = mlen - 1;           // clamp; masked in epilogue
    const int arow = FC1 ? g_perm[seg0 + arow_t] : (seg0 + arow_t);
    const float* aSrc = Agm + (size_t)arow * KTOT + c4b * 4;

    const float* wbase = Wgm + (size_t)e * ((size_t)(FC1 ? FD : HD) * KTOT);
    const float* bSrc0 = wbase + (size_t)(n0 + grow)       * KTOT + c4b * 4;
    const float* bSrc1 = wbase + (size_t)(n0 + grow + 128) * KTOT + c4b * 4;

    // precomputed swizzled smem write offsets (16B granularity; swz: c4 ^= row&7)
    uint32_t offA[4], offB0[4], offB1[4];
#pragma unroll
    for (int j = 0; j < 4; j++) {
        offA[j]  = (uint32_t)grow * 128u + (uint32_t)(((c4b + j) ^ (grow & 7)) << 4);
        offB0[j] = offA[j];
        offB1[j] = (uint32_t)(grow + 128) * 128u +
                   (uint32_t)(((c4b + j) ^ ((grow + 128) & 7)) << 4);
    }

    // ---- ldmatrix per-lane address components ----
    const int lr   = lid & 7;
    const int lmi  = lid >> 3;                 // 0..3 (x4 matrix idx)
    const int rowA0 = wm * 64 + ((lmi & 1) << 3) + lr;
    const int c4Ah  = lmi >> 1;                // + 2*kk
    const int s7A   = rowA0 & 7;
    const int miB   = (lid >> 3) & 1;          // x2 matrix idx
    const int rowB0 = wn * 64 + lr;
    const int s7B   = rowB0 & 7;

    float acc[4][8][4];
#pragma unroll
    for (int i = 0; i < 4; i++)
#pragma unroll
        for (int j = 0; j < 8; j++)
#pragma unroll
            for (int q = 0; q < 4; q++) acc[i][j][q] = 0.f;

    const int T = KTOT / BK;

    // ---- fill helper (lambda-free, macro-ish) ----
    auto fill = [&](int s, int kt) {
        const uint32_t sa = smem_b + (uint32_t)s * STAGE_BYTES;
        const uint32_t sb = sa + A_STAGE_BYTES;
        const float* a  = aSrc  + kt * BK;
        const float* b0 = bSrc0 + kt * BK;
        const float* b1 = bSrc1 + kt * BK;
#pragma unroll
        for (int j = 0; j < 4; j++) cp16(sa + offA[j],  a  + j * 4);
#pragma unroll
        for (int j = 0; j < 4; j++) cp16(sb + offB0[j], b0 + j * 4);
#pragma unroll
        for (int j = 0; j < 4; j++) cp16(sb + offB1[j], b1 + j * 4);
    };

    // prologue: fill stages 0..STAGES-2
#pragma unroll
    for (int s = 0; s < STAGES - 1; s++) { fill(s, s); cp_commit(); }

    for (int kt = 0; kt < T; kt++) {
        cp_wait<STAGES - 2>();
        __syncthreads();

        // issue next fill into the buffer not being read
        if (kt + STAGES - 1 < T) fill((kt + STAGES - 1) % STAGES, kt + STAGES - 1);
        cp_commit();

        const int s = kt % STAGES;
        const uint32_t aBase = smem_b + (uint32_t)s * STAGE_BYTES + (uint32_t)rowA0 * 128u;
        const uint32_t bBase = smem_b + (uint32_t)s * STAGE_BYTES + A_STAGE_BYTES +
                               (uint32_t)rowB0 * 128u;

#pragma unroll
        for (int kk = 0; kk < 4; kk++) {
            uint32_t af[4][4];
            const uint32_t swA = (uint32_t)(((2 * kk + c4Ah) ^ s7A) << 4);
#pragma unroll
            for (int fm = 0; fm < 4; fm++)
                ldsm_x4(af[fm], aBase + (uint32_t)fm * 2048u + swA);

            uint32_t bf[8][2];
            const uint32_t swB = (uint32_t)(((2 * kk + miB) ^ s7B) << 4);
#pragma unroll
            for (int fn = 0; fn < 8; fn++)
                ldsm_x2(bf[fn], bBase + (uint32_t)fn * 1024u + swB);

#pragma unroll
            for (int fm = 0; fm < 4; fm++)
#pragma unroll
                for (int fn = 0; fn < 8; fn++)
                    mma_tf32(acc[fm][fn], af[fm], bf[fn]);
        }
        __syncthreads();
    }

    // ---- epilogue ----
    const int g = lid >> 2;
    const int q = lid & 3;

    if (FC1) {
#pragma unroll
        for (int fm = 0; fm < 4; fm++) {
#pragma unroll
            for (int h = 0; h < 2; h++) {
                const int row = m0 + wm * 64 + fm * 16 + h * 8 + g;
                if (row < mlen) {
                    float* dst = g_hbuf + (size_t)(seg0 + row) * FD + n0 + wn * 64 + q * 2;
#pragma unroll
                    for (int fn = 0; fn < 8; fn++) {
                        float2 v;
                        v.x = f2tf32(gelu_exact(acc[fm][fn][h * 2 + 0]));
                        v.y = f2tf32(gelu_exact(acc[fm][fn][h * 2 + 1]));
                        *(float2*)(dst + fn * 8) = v;
                    }
                }
            }
        }
    } else {
#pragma unroll
        for (int fm = 0; fm < 4; fm++) {
#pragma unroll
            for (int h = 0; h < 2; h++) {
                const int row = m0 + wm * 64 + fm * 16 + h * 8 + g;
                if (row < mlen) {
                    const int orig = g_perm[seg0 + row];
                    const float gg = gate[orig];
                    const int   dest = new_index[orig] >> 1;
                    float* orow = outp + (size_t)dest * HD + n0 + wn * 64 + q * 2;
#pragma unroll
                    for (int fn = 0; fn < 8; fn++) {
                        atomicAdd(orow + fn * 8 + 0, acc[fm][fn][h * 2 + 0] * gg);
                        atomicAdd(orow + fn * 8 + 1, acc[fm][fn][h * 2 + 1] * gg);
                    }
                }
            }
        }
    }
}

// ---------------- launch ----------------
extern "C" void kernel_launch(void* const* d_in, const int* in_sizes, int n_in,
                              void* d_out, int out_size) {
    const float* x         = (const float*)d_in[0];
    const float* gate      = (const float*)d_in[1];
    const int*   experts   = (const int*)  d_in[2];
    const int*   new_index = (const int*)  d_in[3];
    const float* w1        = (const float*)d_in[4];
    const float* w2        = (const float*)d_in[5];
    float*       out       = (float*)d_out;

    static bool attr_set = false;
    // (setting attributes every call is cheap and graph-capture-safe is required;
    //  cudaFuncSetAttribute is a host-side call, allowed)
    cudaFuncSetAttribute(k_gemm<HD, true>,  cudaFuncAttributeMaxDynamicSharedMemorySize, SMEM_BYTES);
    cudaFuncSetAttribute(k_gemm<FD, false>, cudaFuncAttributeMaxDynamicSharedMemorySize, SMEM_BYTES);
    (void)attr_set;

    cudaMemsetAsync(d_out, 0, (size_t)out_size * sizeof(float), 0);

    // routing
    k_zero<<<1, 32>>>();
    k_count<<<NT / 256, 256>>>(experts);
    k_scan<<<1, 1>>>();
    k_scatter<<<NT / 256, 256>>>(experts);

    // tf32 pre-rounding (cvt.rna) of x, w1, w2
    float* w1t; float* w2t; float* xt;
    cudaGetSymbolAddress((void**)&w1t, g_w1t);
    cudaGetSymbolAddress((void**)&w2t, g_w2t);
    cudaGetSymbolAddress((void**)&xt,  g_xt);
    k_cvt<<<4096, 256>>>((const float4*)w1, (float4*)w1t, NE * FD * HD / 4);
    k_cvt<<<4096, 256>>>((const float4*)w2, (float4*)w2t, NE * HD * FD / 4);
    k_cvt<<<2048, 256>>>((const float4*)x,  (float4*)xt,  NT * HD / 4);

    float* hbuf;
    cudaGetSymbolAddress((void**)&hbuf, g_hbuf);

    // fc1: gelu(x @ w1^T) -> g_hbuf   (K = HD)
    k_gemm<HD, true><<<dim3(FD / BN, NT / BM, NE), 256, SMEM_BYTES>>>(
        xt, w1t, gate, new_index, hbuf);
    // fc2: (hbuf @ w2^T) * gate -> scatter-add out  (K = FD)
    k_gemm<FD, false><<<dim3(HD / BN, NT / BM, NE), 256, SMEM_BYTES>>>(
        hbuf, w2t, gate, new_index, out);
}

// round 4
// speedup vs baseline: 4.9056x; 1.7017x over previous
#include <cuda_runtime.h>
#include <cuda_fp16.h>
#include <math.h>
#include <stdint.h>

// ---------------- problem constants ----------------
#define NE 8
#define HD 1024
#define FD 4096
#define NT 8192

// ---------------- GEMM tile config (fp16, m16n8k16) ----------------
#define BM 128
#define BN 256
#define BK 64                                    // 64 halves = 128B row
#define STAGES 3
#define A_STAGE_BYTES (BM * BK * 2)              // 16384
#define B_STAGE_BYTES (BN * BK * 2)              // 32768
#define STAGE_BYTES   (A_STAGE_BYTES + B_STAGE_BYTES)   // 49152
#define SMEM_BYTES    (STAGES * STAGE_BYTES)            // 147456

// ---------------- device scratch ----------------
__device__ __align__(16) __half g_w1h[(size_t)NE * FD * HD];
__device__ __align__(16) __half g_w2h[(size_t)NE * HD * FD];
__device__ __align__(16) __half g_xh[(size_t)NT * HD];
__device__ __align__(16) __half g_hbuf[(size_t)NT * FD];   // gelu(fc1), sorted order
__device__ int g_perm[NT];
__device__ int g_cnt[NE], g_cur[NE], g_off[NE + 1];

// ---------------- helpers ----------------
__device__ __forceinline__ uint32_t smem_u32(const void* p) {
    uint32_t a;
    asm("{ .reg .u64 t; cvta.to.shared.u64 t, %1; cvt.u32.u64 %0, t; }" : "=r"(a) : "l"(p));
    return a;
}
__device__ __forceinline__ void cp16(uint32_t dst, const void* src) {
    asm volatile("cp.async.cg.shared.global [%0], [%1], 16;" :: "r"(dst), "l"(src));
}
__device__ __forceinline__ void cp_commit() {
    asm volatile("cp.async.commit_group;" ::: "memory");
}
template <int N>
__device__ __forceinline__ void cp_wait() {
    asm volatile("cp.async.wait_group %0;" :: "n"(N) : "memory");
}
__device__ __forceinline__ void ldsm_x4(uint32_t* r, uint32_t addr) {
    asm volatile("ldmatrix.sync.aligned.m8n8.x4.shared.b16 {%0,%1,%2,%3}, [%4];"
                 : "=r"(r[0]), "=r"(r[1]), "=r"(r[2]), "=r"(r[3]) : "r"(addr));
}
__device__ __forceinline__ void mma_f16(float* c, const uint32_t* a, uint32_t b0, uint32_t b1) {
    asm volatile(
        "mma.sync.aligned.m16n8k16.row.col.f32.f16.f16.f32 "
        "{%0,%1,%2,%3}, {%4,%5,%6,%7}, {%8,%9}, {%0,%1,%2,%3};"
        : "+f"(c[0]), "+f"(c[1]), "+f"(c[2]), "+f"(c[3])
        : "r"(a[0]), "r"(a[1]), "r"(a[2]), "r"(a[3]), "r"(b0), "r"(b1));
}
__device__ __forceinline__ float gelu_exact(float v) {
    return 0.5f * v * (1.0f + erff(v * 0.7071067811865476f));
}

// ---------------- routing: counting sort by expert ----------------
__global__ void k_zero() {
    int t = threadIdx.x;
    if (t < NE) { g_cnt[t] = 0; g_cur[t] = 0; }
}
__global__ void k_count(const int* __restrict__ ex) {
    int i = blockIdx.x * blockDim.x + threadIdx.x;
    if (i < NT) atomicAdd(&g_cnt[ex[i]], 1);
}
__global__ void k_scan() {
    int s = 0;
    for (int e = 0; e < NE; e++) { g_off[e] = s; s += g_cnt[e]; }
    g_off[NE] = s;
}
__global__ void k_scatter(const int* __restrict__ ex) {
    int i = blockIdx.x * blockDim.x + threadIdx.x;
    if (i < NT) {
        int e = ex[i];
        int r = atomicAdd(&g_cur[e], 1);
        g_perm[g_off[e] + r] = i;
    }
}

// ---------------- fp32 -> fp16 conversion ----------------
__global__ void k_cvt_h(const float4* __restrict__ src, uint4* __restrict__ dst, int n8) {
    // each unit: 8 floats -> 8 halves (16B out)
    int i = blockIdx.x * blockDim.x + threadIdx.x;
    int stride = gridDim.x * blockDim.x;
    for (; i < n8; i += stride) {
        float4 v0 = src[i * 2];
        float4 v1 = src[i * 2 + 1];
        __half2 h0 = __floats2half2_rn(v0.x, v0.y);
        __half2 h1 = __floats2half2_rn(v0.z, v0.w);
        __half2 h2 = __floats2half2_rn(v1.x, v1.y);
        __half2 h3 = __floats2half2_rn(v1.z, v1.w);
        uint4 o;
        o.x = *(uint32_t*)&h0; o.y = *(uint32_t*)&h1;
        o.z = *(uint32_t*)&h2; o.w = *(uint32_t*)&h3;
        dst[i] = o;
    }
}

// ---------------- fp16 mma.sync grouped GEMM ----------------
// FC1: A = gathered g_xh rows [mlen, HD], B = g_w1h[e] [FD, HD] -> gelu -> g_hbuf (fp16)
// FC2: A = g_hbuf rows [mlen, FD],       B = g_w2h[e] [HD, FD] -> gate*scatter-add -> out

template <int KTOT, bool FC1>
__global__ __launch_bounds__(256, 1)
void k_gemm(const __half* __restrict__ Agm,
            const __half* __restrict__ Wgm,
            const float*  __restrict__ gate,
            const int*    __restrict__ new_index,
            float*        __restrict__ outp)
{
    extern __shared__ __align__(128) char smem[];

    const int e    = blockIdx.z;
    const int seg0 = g_off[e];
    const int mlen = g_off[e + 1] - seg0;
    const int m0   = blockIdx.y * BM;
    if (m0 >= mlen) return;
    const int n0   = blockIdx.x * BN;

    const int tid = threadIdx.x;
    const int wid = tid >> 5;
    const int lid = tid & 31;
    const int wm  = wid & 1;       // m half (64 rows)
    const int wn  = wid >> 1;      // n quarter (64 cols)

    const uint32_t smem_b = smem_u32(smem);

    // ---- gmem load mapping: thread t -> row t>>1, 64B half (t&1) of the 128B row ----
    const int grow = tid >> 1;
    const int c4b  = (tid & 1) * 4;      // 16B-chunk base within row (0 or 4)

    int arow_t = m0 + grow;
    if (arow_t >= mlen) arow_t = mlen - 1;          // clamp; masked in epilogue
    const int arow = FC1 ? g_perm[seg0 + arow_t] : (seg0 + arow_t);
    const __half* aSrc = Agm + (size_t)arow * KTOT + c4b * 8;

    const __half* wbase = Wgm + (size_t)e * ((size_t)(FC1 ? FD : HD) * KTOT);
    const __half* bSrc0 = wbase + (size_t)(n0 + grow)       * KTOT + c4b * 8;
    const __half* bSrc1 = wbase + (size_t)(n0 + grow + 128) * KTOT + c4b * 8;

    // swizzled smem write offsets (16B chunks, xor row&7)
    uint32_t offA[4], offB1[4];
#pragma unroll
    for (int j = 0; j < 4; j++) {
        offA[j]  = (uint32_t)grow * 128u + (uint32_t)(((c4b + j) ^ (grow & 7)) << 4);
        offB1[j] = (uint32_t)(grow + 128) * 128u +
                   (uint32_t)(((c4b + j) ^ ((grow + 128) & 7)) << 4);
    }

    // ---- ldmatrix per-lane address components ----
    const int lr  = lid & 7;
    const int lmi = lid >> 3;                  // matrix idx 0..3
    const int rowA0 = wm * 64 + ((lmi & 1) << 3) + lr;
    const int rowB0 = wn * 64 + ((lmi & 1) << 3) + lr;
    const int kHalf = lmi >> 1;                // +2*kk -> 16B chunk
    const int s7A = rowA0 & 7;
    const int s7B = rowB0 & 7;

    float acc[4][8][4];
#pragma unroll
    for (int i = 0; i < 4; i++)
#pragma unroll
        for (int j = 0; j < 8; j++)
#pragma unroll
            for (int q = 0; q < 4; q++) acc[i][j][q] = 0.f;

    const int T = KTOT / BK;

    auto fill = [&](int s, int kt) {
        const uint32_t sa = smem_b + (uint32_t)s * STAGE_BYTES;
        const uint32_t sb = sa + A_STAGE_BYTES;
        const __half* a  = aSrc  + kt * BK;
        const __half* b0 = bSrc0 + kt * BK;
        const __half* b1 = bSrc1 + kt * BK;
#pragma unroll
        for (int j = 0; j < 4; j++) cp16(sa + offA[j],  a  + j * 8);
#pragma unroll
        for (int j = 0; j < 4; j++) cp16(sb + offA[j],  b0 + j * 8);
#pragma unroll
        for (int j = 0; j < 4; j++) cp16(sb + offB1[j], b1 + j * 8);
    };

#pragma unroll
    for (int s = 0; s < STAGES - 1; s++) { fill(s, s); cp_commit(); }

    for (int kt = 0; kt < T; kt++) {
        cp_wait<STAGES - 2>();
        __syncthreads();

        if (kt + STAGES - 1 < T) fill((kt + STAGES - 1) % STAGES, kt + STAGES - 1);
        cp_commit();

        const int s = kt % STAGES;
        const uint32_t aBase = smem_b + (uint32_t)s * STAGE_BYTES + (uint32_t)rowA0 * 128u;
        const uint32_t bBase = smem_b + (uint32_t)s * STAGE_BYTES + A_STAGE_BYTES +
                               (uint32_t)rowB0 * 128u;

#pragma unroll
        for (int kk = 0; kk < 4; kk++) {               // 4 x k16 per BK=64 tile
            const uint32_t swA = (uint32_t)(((2 * kk + kHalf) ^ s7A) << 4);
            const uint32_t swB = (uint32_t)(((2 * kk + kHalf) ^ s7B) << 4);

            uint32_t af[4][4];
#pragma unroll
            for (int fm = 0; fm < 4; fm++)
                ldsm_x4(af[fm], aBase + (uint32_t)fm * 2048u + swA);

            uint32_t bf[4][4];                          // [n16 tile][4 regs]
#pragma unroll
            for (int fn = 0; fn < 4; fn++)
                ldsm_x4(bf[fn], bBase + (uint32_t)fn * 2048u + swB);

#pragma unroll
            for (int fm = 0; fm < 4; fm++)
#pragma unroll
                for (int fn = 0; fn < 4; fn++) {
                    mma_f16(acc[fm][2 * fn + 0], af[fm], bf[fn][0], bf[fn][2]);
                    mma_f16(acc[fm][2 * fn + 1], af[fm], bf[fn][1], bf[fn][3]);
                }
        }
        __syncthreads();
    }

    // ---- epilogue ----
    const int g = lid >> 2;
    const int q = lid & 3;

    if (FC1) {
#pragma unroll
        for (int fm = 0; fm < 4; fm++) {
#pragma unroll
            for (int h = 0; h < 2; h++) {
                const int row = m0 + wm * 64 + fm * 16 + h * 8 + g;
                if (row < mlen) {
                    __half* dst = g_hbuf + (size_t)(seg0 + row) * FD + n0 + wn * 64 + q * 2;
#pragma unroll
                    for (int fn = 0; fn < 8; fn++) {
                        __half2 v = __floats2half2_rn(gelu_exact(acc[fm][fn][h * 2 + 0]),
                                                      gelu_exact(acc[fm][fn][h * 2 + 1]));
                        *(__half2*)(dst + fn * 8) = v;
                    }
                }
            }
        }
    } else {
#pragma unroll
        for (int fm = 0; fm < 4; fm++) {
#pragma unroll
            for (int h = 0; h < 2; h++) {
                const int row = m0 + wm * 64 + fm * 16 + h * 8 + g;
                if (row < mlen) {
                    const int orig = g_perm[seg0 + row];
                    const float gg = gate[orig];
                    const int   dest = new_index[orig] >> 1;
                    float* orow = outp + (size_t)dest * HD + n0 + wn * 64 + q * 2;
#pragma unroll
                    for (int fn = 0; fn < 8; fn++) {
                        atomicAdd(orow + fn * 8 + 0, acc[fm][fn][h * 2 + 0] * gg);
                        atomicAdd(orow + fn * 8 + 1, acc[fm][fn][h * 2 + 1] * gg);
                    }
                }
            }
        }
    }
}

// ---------------- launch ----------------
extern "C" void kernel_launch(void* const* d_in, const int* in_sizes, int n_in,
                              void* d_out, int out_size) {
    const float* x         = (const float*)d_in[0];
    const float* gate      = (const float*)d_in[1];
    const int*   experts   = (const int*)  d_in[2];
    const int*   new_index = (const int*)  d_in[3];
    const float* w1        = (const float*)d_in[4];
    const float* w2        = (const float*)d_in[5];
    float*       out       = (float*)d_out;

    cudaFuncSetAttribute(k_gemm<HD, true>,  cudaFuncAttributeMaxDynamicSharedMemorySize, SMEM_BYTES);
    cudaFuncSetAttribute(k_gemm<FD, false>, cudaFuncAttributeMaxDynamicSharedMemorySize, SMEM_BYTES);

    cudaMemsetAsync(d_out, 0, (size_t)out_size * sizeof(float), 0);

    // routing
    k_zero<<<1, 32>>>();
    k_count<<<NT / 256, 256>>>(experts);
    k_scan<<<1, 1>>>();
    k_scatter<<<NT / 256, 256>>>(experts);

    // fp16 conversion of x, w1, w2
    __half* w1h; __half* w2h; __half* xh; __half* hbuf;
    cudaGetSymbolAddress((void**)&w1h, g_w1h);
    cudaGetSymbolAddress((void**)&w2h, g_w2h);
    cudaGetSymbolAddress((void**)&xh,  g_xh);
    cudaGetSymbolAddress((void**)&hbuf, g_hbuf);
    k_cvt_h<<<4096, 256>>>((const float4*)w1, (uint4*)w1h, NE * FD * HD / 8);
    k_cvt_h<<<4096, 256>>>((const float4*)w2, (uint4*)w2h, NE * HD * FD / 8);
    k_cvt_h<<<1024, 256>>>((const float4*)x,  (uint4*)xh,  NT * HD / 8);

    // fc1: gelu(x @ w1^T) -> g_hbuf   (K = HD)
    k_gemm<HD, true><<<dim3(FD / BN, NT / BM, NE), 256, SMEM_BYTES>>>(
        xh, w1h, gate, new_index, out);
    // fc2: (hbuf @ w2^T) * gate -> scatter-add out  (K = FD)
    k_gemm<FD, false><<<dim3(HD / BN, NT / BM, NE), 256, SMEM_BYTES>>>(
        hbuf, w2h, gate, new_index, out);
}